// round 14
// baseline (speedup 1.0000x reference)
#include <cuda_runtime.h>
#include <math.h>

#define NCH   256
#define OUTSZ 7
#define GRIDY 8                  // channel splits
#define CPB   (NCH / GRIDY)      // 32 channels per block
#define NWARP 8
#define CPW   (CPB / NWARP)      // 4 channels per warp -> one fused body

__global__ __launch_bounds__(256, 5)
void msroi_kernel(const float* __restrict__ f0,
                  const float* __restrict__ f1,
                  const float* __restrict__ f2,
                  const float* __restrict__ f3,
                  const float* __restrict__ boxes,
                  float* __restrict__ out,
                  int nroi)
{
    const int roi = blockIdx.x;
    const int tid = threadIdx.x;

    // per-lane tap tables: 28 taps = 14 grid points x 2 bilinear taps
    __shared__ __align__(16) int   sxc[32];   // x column index per tap
    __shared__ __align__(16) float swx[32];   // x weight per tap (x0.25 fold)
    __shared__ __align__(16) int   sry[28];   // y row offset (elements) per tap
    __shared__ __align__(16) float swy[28];   // y weight per tap
    __shared__ const float* sbase;
    __shared__ int sHW;

    // ---- per-ROI params (computed redundantly by all threads; cheap) ----
    const float bx1 = boxes[roi * 4 + 0];
    const float by1 = boxes[roi * 4 + 1];
    const float bx2 = boxes[roi * 4 + 2];
    const float by2 = boxes[roi * 4 + 3];

    float area = (bx2 - bx1) * (by2 - by1);
    float s    = sqrtf(fmaxf(area, 0.0f));
    float lvlf = floorf(4.0f + log2f(s / 224.0f) + 1e-6f);
    lvlf = fminf(fmaxf(lvlf, 2.0f), 5.0f);
    const int lvl = (int)lvlf - 2;                 // 0..3

    const int   Hs[4]  = {200, 100, 50, 25};
    const float scs[4] = {0.25f, 0.125f, 0.0625f, 0.03125f};
    const int   H = Hs[lvl];
    const int   W = H;
    const float scale = scs[lvl];

    if (tid < 32) {
        // ---- x tap tables (taps 28..31 zero-weight, index 0) ----
        const int g = tid;
        int   xc = 0;
        float w  = 0.0f;
        if (g < 28) {
            const int gx = g >> 1;
            const int xt = g & 1;
            const float c1 = bx1 * scale;
            const float c2 = bx2 * scale;
            const float bin = fmaxf(c2 - c1, 1.0f) / (float)OUTSZ;
            const float coord = c1 + (float)(gx >> 1) * bin
                                   + ((float)(gx & 1) + 0.5f) * bin / 2.0f;
            const bool valid = (coord >= -1.0f) && (coord <= (float)W);
            const float cc = fminf(fmaxf(coord, 0.0f), (float)(W - 1));
            const int i0 = (int)floorf(cc);
            const int i1 = min(i0 + 1, W - 1);
            const float l = cc - (float)i0;
            const float h = 1.0f - l;
            xc = xt ? i1 : i0;
            w  = valid ? (xt ? l : h) * 0.25f : 0.0f;   // fold the 1/4 bin average
        }
        sxc[g] = xc;
        swx[g] = w;
    } else if (tid < 64) {
        // ---- y tap tables ----
        const int g = tid - 32;
        if (g < 28) {
            const int gy = g >> 1;
            const int yt = g & 1;
            const float c1 = by1 * scale;
            const float c2 = by2 * scale;
            const float bin = fmaxf(c2 - c1, 1.0f) / (float)OUTSZ;
            const float coord = c1 + (float)(gy >> 1) * bin
                                   + ((float)(gy & 1) + 0.5f) * bin / 2.0f;
            const bool valid = (coord >= -1.0f) && (coord <= (float)H);
            const float cc = fminf(fmaxf(coord, 0.0f), (float)(H - 1));
            const int i0 = (int)floorf(cc);
            const int i1 = min(i0 + 1, H - 1);
            const float l = cc - (float)i0;
            const float h = 1.0f - l;
            sry[g] = (yt ? i1 : i0) * W;
            swy[g] = valid ? (yt ? l : h) : 0.0f;
        } else if (g == 28) {
            const int perB = nroi >> 1;            // B = 2
            const int b = roi / perB;
            const float* fl = (lvl == 0) ? f0 : (lvl == 1) ? f1
                            : (lvl == 2) ? f2 : f3;
            sHW = H * W;
            sbase = fl + (size_t)b * (size_t)NCH * (size_t)(H * W);
        }
    }
    __syncthreads();

    const int warp = tid >> 5;
    const int lane = tid & 31;

    const int   xc = sxc[lane];
    const float wx = swx[lane];
    const bool  act  = lane < 28;       // lanes 28..31 fully predicated off
    const bool  odd1 = (lane & 1) != 0;
    const bool  odd2 = (lane & 2) != 0;

    const int HW = sHW;
    const int c0 = blockIdx.y * CPB + warp * CPW;
    const float* q = sbase + (size_t)c0 * HW + xc;

    // after the 3-shuffle transpose-reduce, lane (4g+k) holds channel c0+k,
    // bin bx = g  -> identity channel map, contiguous output runs.
    float* o = out + (size_t)roi * (NCH * OUTSZ * OUTSZ)
                   + (size_t)(c0 + (lane & 3)) * (OUTSZ * OUTSZ) + (lane >> 2);

    const int4*   sry4 = (const int4*)sry;
    const float4* swy4 = (const float4*)swy;

    #pragma unroll
    for (int by = 0; by < OUTSZ; ++by) {
        const int4   r = sry4[by];   // one LDS.128, shared by all 4 channels
        const float4 w = swy4[by];   // one LDS.128

        float a = 0.0f, b = 0.0f, c = 0.0f, d = 0.0f;
        if (act) {
            const float* q1 = q + HW;
            const float* q2 = q + 2 * HW;
            const float* q3 = q + 3 * HW;
            // front-batch all 16 independent loads
            const float va0 = __ldg(q  + r.x);
            const float vb0 = __ldg(q1 + r.x);
            const float vc0 = __ldg(q2 + r.x);
            const float vd0 = __ldg(q3 + r.x);
            const float va1 = __ldg(q  + r.y);
            const float vb1 = __ldg(q1 + r.y);
            const float vc1 = __ldg(q2 + r.y);
            const float vd1 = __ldg(q3 + r.y);
            const float va2 = __ldg(q  + r.z);
            const float vb2 = __ldg(q1 + r.z);
            const float vc2 = __ldg(q2 + r.z);
            const float vd2 = __ldg(q3 + r.z);
            const float va3 = __ldg(q  + r.w);
            const float vb3 = __ldg(q1 + r.w);
            const float vc3 = __ldg(q2 + r.w);
            const float vd3 = __ldg(q3 + r.w);

            a =      w.x * va0;
            b =      w.x * vb0;
            c =      w.x * vc0;
            d =      w.x * vd0;
            a = fmaf(w.y, va1, a);
            b = fmaf(w.y, vb1, b);
            c = fmaf(w.y, vc1, c);
            d = fmaf(w.y, vd1, d);
            a = fmaf(w.z, va2, a);
            b = fmaf(w.z, vb2, b);
            c = fmaf(w.z, vc2, c);
            d = fmaf(w.z, vd2, d);
            a = fmaf(w.w, va3, a);
            b = fmaf(w.w, vb3, b);
            c = fmaf(w.w, vc3, c);
            d = fmaf(w.w, vd3, d);
            a *= wx;  b *= wx;  c *= wx;  d *= wx;
        }

        // --- 3-shuffle 4x4 transpose-reduce ---
        float t1 = odd1 ? a : b;
        t1 = __shfl_xor_sync(0xffffffffu, t1, 1);
        const float X = (odd1 ? b : a) + t1;

        float t2 = odd1 ? c : d;
        t2 = __shfl_xor_sync(0xffffffffu, t2, 1);
        const float Y = (odd1 ? d : c) + t2;

        float t3 = odd2 ? X : Y;
        t3 = __shfl_xor_sync(0xffffffffu, t3, 2);
        const float res = (odd2 ? Y : X) + t3;

        if (act) __stcs(o + by * OUTSZ, res);
    }
}

extern "C" void kernel_launch(void* const* d_in, const int* in_sizes, int n_in,
                              void* d_out, int out_size)
{
    const float* f0 = (const float*)d_in[0];
    const float* f1 = (const float*)d_in[1];
    const float* f2 = (const float*)d_in[2];
    const float* f3 = (const float*)d_in[3];
    const float* bx = (const float*)d_in[4];
    float* out = (float*)d_out;

    const int nroi = in_sizes[4] / 4;              // 512
    dim3 grid(nroi, GRIDY, 1);                     // 512 x 8
    msroi_kernel<<<grid, 256>>>(f0, f1, f2, f3, bx, out, nroi);
}

// round 15
// speedup vs baseline: 1.0322x; 1.0322x over previous
#include <cuda_runtime.h>
#include <math.h>

#define NCH   256
#define OUTSZ 7
#define GRIDY 16                 // channel splits
#define CPB   (NCH / GRIDY)      // 16 channels per block
#define NWARP 4                  // 128-thread blocks
#define CPW   (CPB / NWARP)      // 4 channels per warp -> one fused body

__global__ __launch_bounds__(128, 12)
void msroi_kernel(const float* __restrict__ f0,
                  const float* __restrict__ f1,
                  const float* __restrict__ f2,
                  const float* __restrict__ f3,
                  const float* __restrict__ boxes,
                  float* __restrict__ out,
                  int nroi)
{
    const int roi = blockIdx.x;
    const int tid = threadIdx.x;

    // per-lane tap tables: 28 taps = 14 grid points x 2 bilinear taps
    __shared__ __align__(16) int   sxc[32];   // x column index per tap
    __shared__ __align__(16) float swx[32];   // x weight per tap (x0.25 fold)
    __shared__ __align__(16) int   sry[28];   // y row offset (elements) per tap
    __shared__ __align__(16) float swy[28];   // y weight per tap
    __shared__ const float* sbase;
    __shared__ int sHW;

    // ---- per-ROI params (computed redundantly by all threads; cheap) ----
    const float bx1 = boxes[roi * 4 + 0];
    const float by1 = boxes[roi * 4 + 1];
    const float bx2 = boxes[roi * 4 + 2];
    const float by2 = boxes[roi * 4 + 3];

    float area = (bx2 - bx1) * (by2 - by1);
    float s    = sqrtf(fmaxf(area, 0.0f));
    float lvlf = floorf(4.0f + log2f(s / 224.0f) + 1e-6f);
    lvlf = fminf(fmaxf(lvlf, 2.0f), 5.0f);
    const int lvl = (int)lvlf - 2;                 // 0..3

    const int   Hs[4]  = {200, 100, 50, 25};
    const float scs[4] = {0.25f, 0.125f, 0.0625f, 0.03125f};
    const int   H = Hs[lvl];
    const int   W = H;
    const float scale = scs[lvl];

    if (tid < 32) {
        // ---- x tap tables (taps 28..31 zero-weight, index 0) ----
        const int g = tid;
        int   xc = 0;
        float w  = 0.0f;
        if (g < 28) {
            const int gx = g >> 1;
            const int xt = g & 1;
            const float c1 = bx1 * scale;
            const float c2 = bx2 * scale;
            const float bin = fmaxf(c2 - c1, 1.0f) / (float)OUTSZ;
            const float coord = c1 + (float)(gx >> 1) * bin
                                   + ((float)(gx & 1) + 0.5f) * bin / 2.0f;
            const bool valid = (coord >= -1.0f) && (coord <= (float)W);
            const float cc = fminf(fmaxf(coord, 0.0f), (float)(W - 1));
            const int i0 = (int)floorf(cc);
            const int i1 = min(i0 + 1, W - 1);
            const float l = cc - (float)i0;
            const float h = 1.0f - l;
            xc = xt ? i1 : i0;
            w  = valid ? (xt ? l : h) * 0.25f : 0.0f;   // fold the 1/4 bin average
        }
        sxc[g] = xc;
        swx[g] = w;
    } else if (tid < 64) {
        // ---- y tap tables ----
        const int g = tid - 32;
        if (g < 28) {
            const int gy = g >> 1;
            const int yt = g & 1;
            const float c1 = by1 * scale;
            const float c2 = by2 * scale;
            const float bin = fmaxf(c2 - c1, 1.0f) / (float)OUTSZ;
            const float coord = c1 + (float)(gy >> 1) * bin
                                   + ((float)(gy & 1) + 0.5f) * bin / 2.0f;
            const bool valid = (coord >= -1.0f) && (coord <= (float)H);
            const float cc = fminf(fmaxf(coord, 0.0f), (float)(H - 1));
            const int i0 = (int)floorf(cc);
            const int i1 = min(i0 + 1, H - 1);
            const float l = cc - (float)i0;
            const float h = 1.0f - l;
            sry[g] = (yt ? i1 : i0) * W;
            swy[g] = valid ? (yt ? l : h) : 0.0f;
        } else if (g == 28) {
            const int perB = nroi >> 1;            // B = 2
            const int b = roi / perB;
            const float* fl = (lvl == 0) ? f0 : (lvl == 1) ? f1
                            : (lvl == 2) ? f2 : f3;
            sHW = H * W;
            sbase = fl + (size_t)b * (size_t)NCH * (size_t)(H * W);
        }
    }
    __syncthreads();

    const int warp = tid >> 5;
    const int lane = tid & 31;

    const int   xc = sxc[lane];
    const float wx = swx[lane];
    const bool  act  = lane < 28;       // lanes 28..31 fully predicated off
    const bool  odd1 = (lane & 1) != 0;
    const bool  odd2 = (lane & 2) != 0;

    const int HW = sHW;
    const int c0 = blockIdx.y * CPB + warp * CPW;
    const float* q = sbase + (size_t)c0 * HW + xc;

    // after the 3-shuffle transpose-reduce, lane (4g+k) holds channel c0+k,
    // bin bx = g  -> identity channel map, contiguous output runs.
    float* o = out + (size_t)roi * (NCH * OUTSZ * OUTSZ)
                   + (size_t)(c0 + (lane & 3)) * (OUTSZ * OUTSZ) + (lane >> 2);

    const int4*   sry4 = (const int4*)sry;
    const float4* swy4 = (const float4*)swy;

    #pragma unroll
    for (int by = 0; by < OUTSZ; ++by) {
        const int4   r = sry4[by];   // one LDS.128, shared by all 4 channels
        const float4 w = swy4[by];   // one LDS.128

        float a = 0.0f, b = 0.0f, c = 0.0f, d = 0.0f;
        if (act) {
            const float* q1 = q + HW;
            const float* q2 = q + 2 * HW;
            const float* q3 = q + 3 * HW;
            a =      w.x * __ldg(q  + r.x);
            b =      w.x * __ldg(q1 + r.x);
            c =      w.x * __ldg(q2 + r.x);
            d =      w.x * __ldg(q3 + r.x);
            a = fmaf(w.y,  __ldg(q  + r.y), a);
            b = fmaf(w.y,  __ldg(q1 + r.y), b);
            c = fmaf(w.y,  __ldg(q2 + r.y), c);
            d = fmaf(w.y,  __ldg(q3 + r.y), d);
            a = fmaf(w.z,  __ldg(q  + r.z), a);
            b = fmaf(w.z,  __ldg(q1 + r.z), b);
            c = fmaf(w.z,  __ldg(q2 + r.z), c);
            d = fmaf(w.z,  __ldg(q3 + r.z), d);
            a = fmaf(w.w,  __ldg(q  + r.w), a);
            b = fmaf(w.w,  __ldg(q1 + r.w), b);
            c = fmaf(w.w,  __ldg(q2 + r.w), c);
            d = fmaf(w.w,  __ldg(q3 + r.w), d);
            a *= wx;  b *= wx;  c *= wx;  d *= wx;
        }

        // --- 3-shuffle 4x4 transpose-reduce ---
        float t1 = odd1 ? a : b;
        t1 = __shfl_xor_sync(0xffffffffu, t1, 1);
        const float X = (odd1 ? b : a) + t1;

        float t2 = odd1 ? c : d;
        t2 = __shfl_xor_sync(0xffffffffu, t2, 1);
        const float Y = (odd1 ? d : c) + t2;

        float t3 = odd2 ? X : Y;
        t3 = __shfl_xor_sync(0xffffffffu, t3, 2);
        const float res = (odd2 ? Y : X) + t3;

        if (act) __stcs(o + by * OUTSZ, res);
    }
}

extern "C" void kernel_launch(void* const* d_in, const int* in_sizes, int n_in,
                              void* d_out, int out_size)
{
    const float* f0 = (const float*)d_in[0];
    const float* f1 = (const float*)d_in[1];
    const float* f2 = (const float*)d_in[2];
    const float* f3 = (const float*)d_in[3];
    const float* bx = (const float*)d_in[4];
    float* out = (float*)d_out;

    const int nroi = in_sizes[4] / 4;              // 512
    dim3 grid(nroi, GRIDY, 1);                     // 512 x 16
    msroi_kernel<<<grid, 128>>>(f0, f1, f2, f3, bx, out, nroi);
}